// round 15
// baseline (speedup 1.0000x reference)
#include <cuda_runtime.h>
#include <cuda_fp16.h>
#include <cstdint>

#define D_DIM 1024
#define M_DIM 1024
#define N_MAX 16384

#define BM 128
#define BN 128
#define BK 64                       // halves per k-tile = 128 bytes/row
#define STAGES 3
#define NPASS 3
#define TOT_TILES (NPASS * (D_DIM / BK))    // 48

#define STAGE_BYTES (BM * 128 + BN * 128)   // 32 KB (A then B)
#define SMEM_DYN_BYTES (STAGES * STAGE_BYTES)   // 96 KB -> 2 CTA/SM

// ---------------- static device scratch (no allocation allowed) -------------
__device__ __align__(16) float  g_p2[M_DIM];
__device__ __align__(16) __half g_qhi[(size_t)N_MAX * D_DIM];
__device__ __align__(16) __half g_qlo[(size_t)N_MAX * D_DIM];
__device__ __align__(16) __half g_phi[(size_t)M_DIM * D_DIM];
__device__ __align__(16) __half g_plo[(size_t)M_DIM * D_DIM];

// ---------------- helpers ----------------------------------------------------
__device__ __forceinline__ uint32_t smem_to_u32(const void* p) {
    uint32_t a;
    asm("{ .reg .u64 t; cvta.to.shared.u64 t, %1; cvt.u32.u64 %0, t; }" : "=r"(a) : "l"(p));
    return a;
}

__device__ __forceinline__ void cp_async16(uint32_t dst, const void* src) {
    asm volatile("cp.async.cg.shared.global [%0], [%1], 16;" :: "r"(dst), "l"(src) : "memory");
}
#define CP_COMMIT() asm volatile("cp.async.commit_group;" ::: "memory")
#define CP_WAIT(n)  asm volatile("cp.async.wait_group %0;" :: "n"(n) : "memory")

__device__ __forceinline__ void ldsm_x4(uint32_t* r, uint32_t addr) {
    asm volatile("ldmatrix.sync.aligned.m8n8.x4.shared.b16 {%0,%1,%2,%3}, [%4];"
                 : "=r"(r[0]), "=r"(r[1]), "=r"(r[2]), "=r"(r[3]) : "r"(addr));
}

__device__ __forceinline__ void mma16816(float* c, const uint32_t* a, const uint32_t* b) {
    asm volatile(
        "mma.sync.aligned.m16n8k16.row.col.f32.f16.f16.f32 "
        "{%0,%1,%2,%3}, {%4,%5,%6,%7}, {%8,%9}, {%0,%1,%2,%3};"
        : "+f"(c[0]), "+f"(c[1]), "+f"(c[2]), "+f"(c[3])
        : "r"(a[0]), "r"(a[1]), "r"(a[2]), "r"(a[3]), "r"(b[0]), "r"(b[1]));
}

// ---------------------------------------------------------------------------
// Kernel A: split fp32 -> (hi, lo) fp16 pairs for Q and P; fused p2 for P.
// Warp per row, processed in two 4-float4 halves to cut register footprint
// (58 -> ~40 regs) and raise occupancy; stores are fire-and-forget __stcg.
// ---------------------------------------------------------------------------
__global__ __launch_bounds__(256) void convert_kernel(const float* __restrict__ q,
                                                      const float* __restrict__ p, int nq) {
    const int row  = blockIdx.x * 8 + (threadIdx.x >> 5);
    const int lane = threadIdx.x & 31;
    const bool isQ = row < nq;
    const float* src = isQ ? (q + (size_t)row * D_DIM) : (p + (size_t)(row - nq) * D_DIM);
    __half* dhi = isQ ? (g_qhi + (size_t)row * D_DIM) : (g_phi + (size_t)(row - nq) * D_DIM);
    __half* dlo = isQ ? (g_qlo + (size_t)row * D_DIM) : (g_plo + (size_t)(row - nq) * D_DIM);

    float s = 0.0f;
    #pragma unroll
    for (int hf = 0; hf < 2; hf++) {
        float4 v[4];
        #pragma unroll
        for (int g = 0; g < 2; g++) {
            const int idx = (hf * 2 + g) * 256 + lane * 8;
            v[2 * g + 0] = __ldcg(reinterpret_cast<const float4*>(src + idx));
            v[2 * g + 1] = __ldcg(reinterpret_cast<const float4*>(src + idx + 4));
        }
        #pragma unroll
        for (int g = 0; g < 2; g++) {
            const int idx = (hf * 2 + g) * 256 + lane * 8;
            const float* f = reinterpret_cast<const float*>(&v[2 * g]);
            __half h[8], l[8];
            #pragma unroll
            for (int e = 0; e < 8; e++) {
                h[e] = __float2half_rn(f[e]);
                l[e] = __float2half_rn(f[e] - __half2float(h[e]));
            }
            __stcg(reinterpret_cast<uint4*>(dhi + idx), *reinterpret_cast<const uint4*>(h));
            __stcg(reinterpret_cast<uint4*>(dlo + idx), *reinterpret_cast<const uint4*>(l));
        }
        #pragma unroll
        for (int j = 0; j < 4; j++)
            s += v[j].x * v[j].x + v[j].y * v[j].y + v[j].z * v[j].z + v[j].w * v[j].w;
    }

    if (!isQ) {                                 // fused p2 (exact fp32)
        #pragma unroll
        for (int o = 16; o; o >>= 1) s += __shfl_xor_sync(0xffffffffu, s, o);
        if (lane == 0) g_p2[row - nq] = s;
    }
}

// ---------------------------------------------------------------------------
// Kernel B: HMMA GEMM (proven R8/R11 config — FROZEN).
// DO NOT reorder wait/barrier: cp.async completion is per-thread; CP_WAIT
// must precede __syncthreads to make other threads' loads visible.
// qp = Qhi*Phi^T + Qhi*Plo^T + Qlo*Phi^T -> out
// ---------------------------------------------------------------------------
struct LoadSlots { uint32_t dst[4]; int src[4]; };

__device__ __forceinline__ void load_tile(int t, uint32_t smem0,
                                          const __half* const* passA,
                                          const __half* const* passB,
                                          const LoadSlots& ls) {
    const int stage = t % STAGES;
    const __half* A = passA[t >> 4] + (t & 15) * BK;
    const __half* B = passB[t >> 4] + (t & 15) * BK;
    const uint32_t sa = smem0 + stage * STAGE_BYTES;
    const uint32_t sb = sa + BM * 128;
    #pragma unroll
    for (int i = 0; i < 4; i++) cp_async16(sa + ls.dst[i], A + ls.src[i]);
    #pragma unroll
    for (int i = 0; i < 4; i++) cp_async16(sb + ls.dst[i], B + ls.src[i]);
}

__global__ __launch_bounds__(256, 2) void gemm_kernel(float* __restrict__ out) {
    extern __shared__ __align__(128) char dsm[];
    const int tid  = threadIdx.x;
    const int lane = tid & 31;
    const int wid  = tid >> 5;
    const int wm   = wid & 1;       // 2 warps along M
    const int wn   = wid >> 1;      // 4 warps along N
    const int brow = blockIdx.y * BM;
    const int bcol = blockIdx.x * BN;

    const uint32_t smem0 = smem_to_u32(dsm);

    LoadSlots ls;
    #pragma unroll
    for (int i = 0; i < 4; i++) {
        int idx = i * 256 + tid, r = idx >> 3, c = idx & 7;
        uint32_t off = (uint32_t)(r * 128 + c * 16);
        ls.dst[i] = off ^ ((off >> 3) & 0x70);
        ls.src[i] = r * D_DIM + c * 8;
    }

    const __half* passA[NPASS] = {g_qhi + (size_t)brow * D_DIM,
                                  g_qhi + (size_t)brow * D_DIM,
                                  g_qlo + (size_t)brow * D_DIM};
    const __half* passB[NPASS] = {g_phi + (size_t)bcol * D_DIM,
                                  g_plo + (size_t)bcol * D_DIM,
                                  g_phi + (size_t)bcol * D_DIM};

    // ldmatrix per-thread addressing (XOR-swizzled 128B rows).
    const int a_row  = wm * 64 + (lane & 15);
    const uint32_t a_base = (uint32_t)(a_row * 128);
    const uint32_t a_xor  = (uint32_t)((a_row & 7) << 4);
    const uint32_t a_sel  = (lane & 16) ? 16u : 0u;
    const int b_row  = wn * 32 + (lane & 7) + ((lane & 16) ? 8 : 0);
    const uint32_t b_base = (uint32_t)(BM * 128 + b_row * 128);
    const uint32_t b_xor  = (uint32_t)((b_row & 7) << 4);
    const uint32_t b_sel  = (lane & 8) ? 16u : 0u;

    float acc[4][4][4];
    #pragma unroll
    for (int i = 0; i < 4; i++)
        #pragma unroll
        for (int j = 0; j < 4; j++)
            #pragma unroll
            for (int k = 0; k < 4; k++) acc[i][j][k] = 0.0f;

    #pragma unroll
    for (int t = 0; t < STAGES - 1; t++) {
        load_tile(t, smem0, passA, passB, ls);
        CP_COMMIT();
    }

    for (int t = 0; t < TOT_TILES; t++) {
        CP_WAIT(STAGES - 2);        // own loads for tile t done...
        __syncthreads();            // ...and everyone else's (visibility fence)
        if (t + STAGES - 1 < TOT_TILES)
            load_tile(t + STAGES - 1, smem0, passA, passB, ls);
        CP_COMMIT();

        const uint32_t sbase = smem0 + (t % STAGES) * STAGE_BYTES;
        #pragma unroll
        for (int ks = 0; ks < BK / 16; ks++) {
            uint32_t af[4][4], bf[2][4];
            #pragma unroll
            for (int mi = 0; mi < 4; mi++)
                ldsm_x4(af[mi], sbase + a_base + mi * 16 * 128 +
                                ((ks * 32 + a_sel) ^ a_xor));
            #pragma unroll
            for (int ni = 0; ni < 2; ni++)
                ldsm_x4(bf[ni], sbase + b_base + ni * 16 * 128 +
                                ((ks * 32 + b_sel) ^ b_xor));
            #pragma unroll
            for (int mi = 0; mi < 4; mi++)
                #pragma unroll
                for (int nj = 0; nj < 4; nj++)
                    mma16816(acc[mi][nj], af[mi], &bf[nj >> 1][(nj & 1) * 2]);
        }
    }

    // Epilogue: store raw qp streaming (only re-read via __ldcg in softmax).
    #pragma unroll
    for (int mi = 0; mi < 4; mi++) {
        #pragma unroll
        for (int nj = 0; nj < 4; nj++) {
            const int r = brow + wm * 64 + mi * 16 + (lane >> 2);
            const int c = bcol + wn * 32 + nj * 8 + (lane & 3) * 2;
            __stcg(reinterpret_cast<float2*>(out + (size_t)r * M_DIM + c),
                   make_float2(acc[mi][nj][0], acc[mi][nj][1]));
            __stcg(reinterpret_cast<float2*>(out + (size_t)(r + 8) * M_DIM + c),
                   make_float2(acc[mi][nj][2], acc[mi][nj][3]));
        }
    }
}

// ---------------------------------------------------------------------------
// Kernel C: in-place row softmax of s[m] = 2*qp[n,m] - p2[m]. Warp per row.
// Hybrid register cache: first half cached, second half recomputed (L2-hot).
// ---------------------------------------------------------------------------
__global__ __launch_bounds__(256) void softmax_kernel(float* __restrict__ out) {
    const int warp = threadIdx.x >> 5, lane = threadIdx.x & 31;
    const int row  = blockIdx.x * 8 + warp;
    float4* p = reinterpret_cast<float4*>(out + (size_t)row * M_DIM);
    const float4* pp = reinterpret_cast<const float4*>(g_p2);

    float sc[16];
    float m = -3.4e38f, sum = 0.0f;
    #pragma unroll
    for (int j = 0; j < 8; j++) {
        float4 v = __ldcg(&p[lane + 32 * j]);
        float4 q = pp[lane + 32 * j];
        float s0 = 2.0f * v.x - q.x, s1 = 2.0f * v.y - q.y;
        float s2 = 2.0f * v.z - q.z, s3 = 2.0f * v.w - q.w;
        if (j < 4) { sc[4*j] = s0; sc[4*j+1] = s1; sc[4*j+2] = s2; sc[4*j+3] = s3; }
        float m4 = fmaxf(fmaxf(s0, s1), fmaxf(s2, s3));
        float mn = fmaxf(m, m4);
        sum = sum * __expf(m - mn)
            + __expf(s0 - mn) + __expf(s1 - mn)
            + __expf(s2 - mn) + __expf(s3 - mn);
        m = mn;
    }
    #pragma unroll
    for (int o = 16; o; o >>= 1) {
        float mo = __shfl_xor_sync(0xffffffffu, m, o);
        float so = __shfl_xor_sync(0xffffffffu, sum, o);
        float mn = fmaxf(m, mo);
        sum = sum * __expf(m - mn) + so * __expf(mo - mn);
        m = mn;
    }
    const float inv = 1.0f / sum;

    #pragma unroll
    for (int j = 0; j < 4; j++) {
        float4 r;
        r.x = __expf(sc[4*j]   - m) * inv;
        r.y = __expf(sc[4*j+1] - m) * inv;
        r.z = __expf(sc[4*j+2] - m) * inv;
        r.w = __expf(sc[4*j+3] - m) * inv;
        p[lane + 32 * j] = r;
    }
    #pragma unroll
    for (int j = 4; j < 8; j++) {
        float4 v = __ldcg(&p[lane + 32 * j]);
        float4 q = pp[lane + 32 * j];
        float4 r;
        r.x = __expf(2.0f * v.x - q.x - m) * inv;
        r.y = __expf(2.0f * v.y - q.y - m) * inv;
        r.z = __expf(2.0f * v.z - q.z - m) * inv;
        r.w = __expf(2.0f * v.w - q.w - m) * inv;
        p[lane + 32 * j] = r;
    }
}

// ---------------------------------------------------------------------------
extern "C" void kernel_launch(void* const* d_in, const int* in_sizes, int n_in,
                              void* d_out, int out_size) {
    const float* query = (const float*)d_in[0];   // [N, 1024] fp32
    const float* proto = (const float*)d_in[1];   // [1024, 1024] fp32
    float* out = (float*)d_out;                   // [N, 1024] fp32
    const int N = in_sizes[0] / D_DIM;

    cudaFuncSetAttribute(gemm_kernel, cudaFuncAttributeMaxDynamicSharedMemorySize,
                         SMEM_DYN_BYTES);

    convert_kernel<<<(N + M_DIM) / 8, 256>>>(query, proto, N);

    dim3 grid(M_DIM / BN, N / BM);                // (8, 128)
    gemm_kernel<<<grid, 256, SMEM_DYN_BYTES>>>(out);

    softmax_kernel<<<N / 8, 256>>>(out);
}

// round 16
// speedup vs baseline: 1.0091x; 1.0091x over previous
#include <cuda_runtime.h>
#include <cuda_fp16.h>
#include <cstdint>

#define D_DIM 1024
#define M_DIM 1024
#define N_MAX 16384

#define BM 128
#define BN 128
#define BK 64                       // halves per k-tile = 128 bytes/row
#define STAGES 3
#define NPASS 3
#define TOT_TILES (NPASS * (D_DIM / BK))    // 48

#define STAGE_BYTES (BM * 128 + BN * 128)   // 32 KB (A then B)
#define SMEM_DYN_BYTES (STAGES * STAGE_BYTES)   // 96 KB -> 2 CTA/SM

// ---------------- static device scratch (no allocation allowed) -------------
__device__ __align__(16) float  g_p2[M_DIM];
__device__ __align__(16) __half g_qhi[(size_t)N_MAX * D_DIM];
__device__ __align__(16) __half g_qlo[(size_t)N_MAX * D_DIM];
__device__ __align__(16) __half g_phi[(size_t)M_DIM * D_DIM];
__device__ __align__(16) __half g_plo[(size_t)M_DIM * D_DIM];

// ---------------- helpers ----------------------------------------------------
__device__ __forceinline__ uint32_t smem_to_u32(const void* p) {
    uint32_t a;
    asm("{ .reg .u64 t; cvta.to.shared.u64 t, %1; cvt.u32.u64 %0, t; }" : "=r"(a) : "l"(p));
    return a;
}

__device__ __forceinline__ void cp_async16(uint32_t dst, const void* src) {
    asm volatile("cp.async.cg.shared.global [%0], [%1], 16;" :: "r"(dst), "l"(src) : "memory");
}
#define CP_COMMIT() asm volatile("cp.async.commit_group;" ::: "memory")
#define CP_WAIT(n)  asm volatile("cp.async.wait_group %0;" :: "n"(n) : "memory")

__device__ __forceinline__ void ldsm_x4(uint32_t* r, uint32_t addr) {
    asm volatile("ldmatrix.sync.aligned.m8n8.x4.shared.b16 {%0,%1,%2,%3}, [%4];"
                 : "=r"(r[0]), "=r"(r[1]), "=r"(r[2]), "=r"(r[3]) : "r"(addr));
}

__device__ __forceinline__ void mma16816(float* c, const uint32_t* a, const uint32_t* b) {
    asm volatile(
        "mma.sync.aligned.m16n8k16.row.col.f32.f16.f16.f32 "
        "{%0,%1,%2,%3}, {%4,%5,%6,%7}, {%8,%9}, {%0,%1,%2,%3};"
        : "+f"(c[0]), "+f"(c[1]), "+f"(c[2]), "+f"(c[3])
        : "r"(a[0]), "r"(a[1]), "r"(a[2]), "r"(a[3]), "r"(b[0]), "r"(b[1]));
}

// ---------------------------------------------------------------------------
// Kernel A: split fp32 -> (hi, lo) fp16 pairs for Q and P; fused p2 for P.
// Warp per row, two 4-float4 halves (38 regs); fire-and-forget __stcg stores.
// ---------------------------------------------------------------------------
__global__ __launch_bounds__(256) void convert_kernel(const float* __restrict__ q,
                                                      const float* __restrict__ p, int nq) {
    const int row  = blockIdx.x * 8 + (threadIdx.x >> 5);
    const int lane = threadIdx.x & 31;
    const bool isQ = row < nq;
    const float* src = isQ ? (q + (size_t)row * D_DIM) : (p + (size_t)(row - nq) * D_DIM);
    __half* dhi = isQ ? (g_qhi + (size_t)row * D_DIM) : (g_phi + (size_t)(row - nq) * D_DIM);
    __half* dlo = isQ ? (g_qlo + (size_t)row * D_DIM) : (g_plo + (size_t)(row - nq) * D_DIM);

    float s = 0.0f;
    #pragma unroll
    for (int hf = 0; hf < 2; hf++) {
        float4 v[4];
        #pragma unroll
        for (int g = 0; g < 2; g++) {
            const int idx = (hf * 2 + g) * 256 + lane * 8;
            v[2 * g + 0] = __ldcg(reinterpret_cast<const float4*>(src + idx));
            v[2 * g + 1] = __ldcg(reinterpret_cast<const float4*>(src + idx + 4));
        }
        #pragma unroll
        for (int g = 0; g < 2; g++) {
            const int idx = (hf * 2 + g) * 256 + lane * 8;
            const float* f = reinterpret_cast<const float*>(&v[2 * g]);
            __half h[8], l[8];
            #pragma unroll
            for (int e = 0; e < 8; e++) {
                h[e] = __float2half_rn(f[e]);
                l[e] = __float2half_rn(f[e] - __half2float(h[e]));
            }
            __stcg(reinterpret_cast<uint4*>(dhi + idx), *reinterpret_cast<const uint4*>(h));
            __stcg(reinterpret_cast<uint4*>(dlo + idx), *reinterpret_cast<const uint4*>(l));
        }
        #pragma unroll
        for (int j = 0; j < 4; j++)
            s += v[j].x * v[j].x + v[j].y * v[j].y + v[j].z * v[j].z + v[j].w * v[j].w;
    }

    if (!isQ) {                                 // fused p2 (exact fp32)
        #pragma unroll
        for (int o = 16; o; o >>= 1) s += __shfl_xor_sync(0xffffffffu, s, o);
        if (lane == 0) g_p2[row - nq] = s;
    }
}

// ---------------------------------------------------------------------------
// Kernel B: HMMA GEMM (proven R8/R11 config — FROZEN).
// DO NOT reorder wait/barrier: cp.async completion is per-thread; CP_WAIT
// must precede __syncthreads to make other threads' loads visible.
// qp = Qhi*Phi^T + Qhi*Plo^T + Qlo*Phi^T -> out
// ---------------------------------------------------------------------------
struct LoadSlots { uint32_t dst[4]; int src[4]; };

__device__ __forceinline__ void load_tile(int t, uint32_t smem0,
                                          const __half* const* passA,
                                          const __half* const* passB,
                                          const LoadSlots& ls) {
    const int stage = t % STAGES;
    const __half* A = passA[t >> 4] + (t & 15) * BK;
    const __half* B = passB[t >> 4] + (t & 15) * BK;
    const uint32_t sa = smem0 + stage * STAGE_BYTES;
    const uint32_t sb = sa + BM * 128;
    #pragma unroll
    for (int i = 0; i < 4; i++) cp_async16(sa + ls.dst[i], A + ls.src[i]);
    #pragma unroll
    for (int i = 0; i < 4; i++) cp_async16(sb + ls.dst[i], B + ls.src[i]);
}

__global__ __launch_bounds__(256, 2) void gemm_kernel(float* __restrict__ out) {
    extern __shared__ __align__(128) char dsm[];
    const int tid  = threadIdx.x;
    const int lane = tid & 31;
    const int wid  = tid >> 5;
    const int wm   = wid & 1;       // 2 warps along M
    const int wn   = wid >> 1;      // 4 warps along N
    const int brow = blockIdx.y * BM;
    const int bcol = blockIdx.x * BN;

    const uint32_t smem0 = smem_to_u32(dsm);

    LoadSlots ls;
    #pragma unroll
    for (int i = 0; i < 4; i++) {
        int idx = i * 256 + tid, r = idx >> 3, c = idx & 7;
        uint32_t off = (uint32_t)(r * 128 + c * 16);
        ls.dst[i] = off ^ ((off >> 3) & 0x70);
        ls.src[i] = r * D_DIM + c * 8;
    }

    const __half* passA[NPASS] = {g_qhi + (size_t)brow * D_DIM,
                                  g_qhi + (size_t)brow * D_DIM,
                                  g_qlo + (size_t)brow * D_DIM};
    const __half* passB[NPASS] = {g_phi + (size_t)bcol * D_DIM,
                                  g_plo + (size_t)bcol * D_DIM,
                                  g_phi + (size_t)bcol * D_DIM};

    // ldmatrix per-thread addressing (XOR-swizzled 128B rows).
    const int a_row  = wm * 64 + (lane & 15);
    const uint32_t a_base = (uint32_t)(a_row * 128);
    const uint32_t a_xor  = (uint32_t)((a_row & 7) << 4);
    const uint32_t a_sel  = (lane & 16) ? 16u : 0u;
    const int b_row  = wn * 32 + (lane & 7) + ((lane & 16) ? 8 : 0);
    const uint32_t b_base = (uint32_t)(BM * 128 + b_row * 128);
    const uint32_t b_xor  = (uint32_t)((b_row & 7) << 4);
    const uint32_t b_sel  = (lane & 8) ? 16u : 0u;

    float acc[4][4][4];
    #pragma unroll
    for (int i = 0; i < 4; i++)
        #pragma unroll
        for (int j = 0; j < 4; j++)
            #pragma unroll
            for (int k = 0; k < 4; k++) acc[i][j][k] = 0.0f;

    #pragma unroll
    for (int t = 0; t < STAGES - 1; t++) {
        load_tile(t, smem0, passA, passB, ls);
        CP_COMMIT();
    }

    for (int t = 0; t < TOT_TILES; t++) {
        CP_WAIT(STAGES - 2);        // own loads for tile t done...
        __syncthreads();            // ...and everyone else's (visibility fence)
        if (t + STAGES - 1 < TOT_TILES)
            load_tile(t + STAGES - 1, smem0, passA, passB, ls);
        CP_COMMIT();

        const uint32_t sbase = smem0 + (t % STAGES) * STAGE_BYTES;
        #pragma unroll
        for (int ks = 0; ks < BK / 16; ks++) {
            uint32_t af[4][4], bf[2][4];
            #pragma unroll
            for (int mi = 0; mi < 4; mi++)
                ldsm_x4(af[mi], sbase + a_base + mi * 16 * 128 +
                                ((ks * 32 + a_sel) ^ a_xor));
            #pragma unroll
            for (int ni = 0; ni < 2; ni++)
                ldsm_x4(bf[ni], sbase + b_base + ni * 16 * 128 +
                                ((ks * 32 + b_sel) ^ b_xor));
            #pragma unroll
            for (int mi = 0; mi < 4; mi++)
                #pragma unroll
                for (int nj = 0; nj < 4; nj++)
                    mma16816(acc[mi][nj], af[mi], &bf[nj >> 1][(nj & 1) * 2]);
        }
    }

    // Epilogue: store raw qp streaming (only re-read via __ldcg in softmax).
    #pragma unroll
    for (int mi = 0; mi < 4; mi++) {
        #pragma unroll
        for (int nj = 0; nj < 4; nj++) {
            const int r = brow + wm * 64 + mi * 16 + (lane >> 2);
            const int c = bcol + wn * 32 + nj * 8 + (lane & 3) * 2;
            __stcg(reinterpret_cast<float2*>(out + (size_t)r * M_DIM + c),
                   make_float2(acc[mi][nj][0], acc[mi][nj][1]));
            __stcg(reinterpret_cast<float2*>(out + (size_t)(r + 8) * M_DIM + c),
                   make_float2(acc[mi][nj][2], acc[mi][nj][3]));
        }
    }
}

// ---------------------------------------------------------------------------
// Kernel C: in-place row softmax of s[m] = 2*qp[n,m] - p2[m]. Warp per row.
// Full row staged in an smem cache during pass 1 (one global read per logit
// -- the traffic floor); pass 2 reads smem, writes global. No block barriers
// (each warp touches only its own 4KB slice).
// ---------------------------------------------------------------------------
__global__ __launch_bounds__(256) void softmax_kernel(float* __restrict__ out) {
    __shared__ float4 cache[8][M_DIM / 4];     // 32 KB: 4 KB per warp-row
    const int warp = threadIdx.x >> 5, lane = threadIdx.x & 31;
    const int row  = blockIdx.x * 8 + warp;
    float4* p = reinterpret_cast<float4*>(out + (size_t)row * M_DIM);
    const float4* pp = reinterpret_cast<const float4*>(g_p2);

    // Pass 1: single global read, logits -> smem, online max/sum.
    float m = -3.4e38f, sum = 0.0f;
    #pragma unroll
    for (int j = 0; j < 8; j++) {
        float4 v = __ldcg(&p[lane + 32 * j]);
        float4 q = pp[lane + 32 * j];
        float4 sv;
        sv.x = 2.0f * v.x - q.x;  sv.y = 2.0f * v.y - q.y;
        sv.z = 2.0f * v.z - q.z;  sv.w = 2.0f * v.w - q.w;
        cache[warp][lane + 32 * j] = sv;
        float m4 = fmaxf(fmaxf(sv.x, sv.y), fmaxf(sv.z, sv.w));
        float mn = fmaxf(m, m4);
        sum = sum * __expf(m - mn)
            + __expf(sv.x - mn) + __expf(sv.y - mn)
            + __expf(sv.z - mn) + __expf(sv.w - mn);
        m = mn;
    }
    #pragma unroll
    for (int o = 16; o; o >>= 1) {
        float mo = __shfl_xor_sync(0xffffffffu, m, o);
        float so = __shfl_xor_sync(0xffffffffu, sum, o);
        float mn = fmaxf(m, mo);
        sum = sum * __expf(m - mn) + so * __expf(mo - mn);
        m = mn;
    }
    const float inv = 1.0f / sum;

    // Pass 2: smem -> exp -> global write.
    #pragma unroll
    for (int j = 0; j < 8; j++) {
        float4 sv = cache[warp][lane + 32 * j];
        float4 r;
        r.x = __expf(sv.x - m) * inv;
        r.y = __expf(sv.y - m) * inv;
        r.z = __expf(sv.z - m) * inv;
        r.w = __expf(sv.w - m) * inv;
        p[lane + 32 * j] = r;
    }
}

// ---------------------------------------------------------------------------
extern "C" void kernel_launch(void* const* d_in, const int* in_sizes, int n_in,
                              void* d_out, int out_size) {
    const float* query = (const float*)d_in[0];   // [N, 1024] fp32
    const float* proto = (const float*)d_in[1];   // [1024, 1024] fp32
    float* out = (float*)d_out;                   // [N, 1024] fp32
    const int N = in_sizes[0] / D_DIM;

    cudaFuncSetAttribute(gemm_kernel, cudaFuncAttributeMaxDynamicSharedMemorySize,
                         SMEM_DYN_BYTES);

    convert_kernel<<<(N + M_DIM) / 8, 256>>>(query, proto, N);

    dim3 grid(M_DIM / BN, N / BM);                // (8, 128)
    gemm_kernel<<<grid, 256, SMEM_DYN_BYTES>>>(out);

    softmax_kernel<<<N / 8, 256>>>(out);
}